// round 5
// baseline (speedup 1.0000x reference)
#include <cuda_runtime.h>
#include <cstdint>

#define B 16
#define CI 64
#define CO 64
#define HH 192
#define WW 192
#define KDY 4
#define HID 17
#define GROUPS 8
#define CPG 8
#define PLANE (HH*WW)
#define TEMPERATURE 30.0f
#define EPS 1e-5f
#define SLOPE 0.01f

// conv tiling
#define CCH 8                      // ci per chunk
#define NCH 8                      // chunks
#define NBUF 3                     // pipeline depth (single-sync safe)
#define SXPS 440                   // sx plane stride (floats) per ci: 6*72 + 8 pad
#define SXB (CCH*SXPS*4)           // 14080 B per sx buffer
#define SBROW 72                   // sb row stride (floats)
#define SBB (9*CCH*SBROW*4)        // 20736 B per sb buffer
#define SMEM_DYN (NBUF*(SXB+SBB))  // 104448 B

// ---- device scratch ----
__device__ float g_pooled[B][CI];
__device__ float g_attn[B][KDY];
__device__ __align__(16) float g_filters[B*NCH*9*CCH*CO];  // [b][cc][tap][ci8][co]
__device__ float g_stats[B][GROUPS][2];

__device__ __forceinline__ uint32_t f2tf32(float v) {
    uint32_t u;
    asm("cvt.rna.tf32.f32 %0, %1;" : "=r"(u) : "f"(v));
    return u;
}
__device__ __forceinline__ void mma8(float* c, const uint32_t* a, const uint32_t* b) {
    asm volatile(
        "mma.sync.aligned.m16n8k8.row.col.f32.tf32.tf32.f32 "
        "{%0,%1,%2,%3}, {%4,%5,%6,%7}, {%8,%9}, {%0,%1,%2,%3};"
        : "+f"(c[0]), "+f"(c[1]), "+f"(c[2]), "+f"(c[3])
        : "r"(a[0]), "r"(a[1]), "r"(a[2]), "r"(a[3]), "r"(b[0]), "r"(b[1]));
}
__device__ __forceinline__ void cpa16(void* dst, const void* src, int sz) {
    uint32_t d = (uint32_t)__cvta_generic_to_shared(dst);
    asm volatile("cp.async.cg.shared.global [%0], [%1], 16, %2;"
                 :: "r"(d), "l"(src), "r"(sz) : "memory");
}
__device__ __forceinline__ void cpa_commit() {
    asm volatile("cp.async.commit_group;" ::: "memory");
}
__device__ __forceinline__ void cpa_wait1() {
    asm volatile("cp.async.wait_group 1;" ::: "memory");
}

// ============================================================
// K1: global average pool
// ============================================================
__global__ void pool_kernel(const float* __restrict__ x) {
    int bc = blockIdx.x;
    const float4* p = (const float4*)(x + (size_t)bc * PLANE);
    float s = 0.f;
    for (int i = threadIdx.x; i < PLANE/4; i += 256) {
        float4 v = p[i];
        s += v.x + v.y + v.z + v.w;
    }
    __shared__ float sm[8];
    #pragma unroll
    for (int o = 16; o > 0; o >>= 1) s += __shfl_down_sync(~0u, s, o);
    if ((threadIdx.x & 31) == 0) sm[threadIdx.x >> 5] = s;
    __syncthreads();
    if (threadIdx.x == 0) {
        float t = 0.f;
        #pragma unroll
        for (int w = 0; w < 8; w++) t += sm[w];
        g_pooled[bc / CI][bc % CI] = t / (float)PLANE;
    }
}

// ============================================================
// K2a: attention MLP + softmax; zero group stats
// ============================================================
__global__ void attn_kernel(const float* __restrict__ w1,
                            const float* __restrict__ w2,
                            const float* __restrict__ b2) {
    int t = threadIdx.x;
    if (t < B * GROUPS * 2) ((float*)g_stats)[t] = 0.f;
    if (t < B) {
        float h[HID];
        #pragma unroll
        for (int j = 0; j < HID; j++) {
            float a = 0.f;
            #pragma unroll 8
            for (int c = 0; c < CI; c++) a += g_pooled[t][c] * w1[j*CI + c];
            h[j] = a > 0.f ? a : 0.f;
        }
        float sc[KDY];
        float m = -1e30f;
        #pragma unroll
        for (int k = 0; k < KDY; k++) {
            float a = b2[k];
            #pragma unroll
            for (int j = 0; j < HID; j++) a += h[j] * w2[k*HID + j];
            sc[k] = a / TEMPERATURE;
            m = fmaxf(m, sc[k]);
        }
        float se = 0.f;
        #pragma unroll
        for (int k = 0; k < KDY; k++) { sc[k] = expf(sc[k] - m); se += sc[k]; }
        #pragma unroll
        for (int k = 0; k < KDY; k++) g_attn[t][k] = sc[k] / se;
    }
}

// ============================================================
// K2b: filter synthesis -> staging layout [b][cc][tap][ci8][co]
// ============================================================
__global__ void filt_kernel(const float* __restrict__ W) {
    int idx = blockIdx.x * 256 + threadIdx.x;
    int co  = idx & 63;
    int ci8 = (idx >> 6) & 7;
    int t3  = idx >> 9;
    int tap = t3 % 9;
    int t4  = t3 / 9;
    int cc  = t4 & 7;
    int b   = t4 >> 3;
    int ci  = cc*CCH + ci8;
    const int ks = CO*CI*9;
    float a0 = g_attn[b][0], a1 = g_attn[b][1], a2 = g_attn[b][2], a3 = g_attn[b][3];
    int wb = (co*CI + ci)*9 + tap;                // W[k][co][ci][tap]
    float f = a0*W[wb] + a1*W[wb+ks] + a2*W[wb+2*ks] + a3*W[wb+3*ks];
    g_filters[idx] = __uint_as_float(f2tf32(f));
}

// ============================================================
// K3: implicit-GEMM tf32 conv, cp.async 3-stage pipeline,
// ONE __syncthreads per chunk.
// CTA: sample b, 256 pixels (4 rows x 64 cols), 64 c_out, 8 warps.
// ============================================================
__global__ void __launch_bounds__(256, 2)
conv_kernel(const float* __restrict__ x, float* __restrict__ out) {
    extern __shared__ __align__(16) unsigned char dynsm[];
    float* sxb[NBUF];
    float* sbb[NBUF];
    #pragma unroll
    for (int i = 0; i < NBUF; i++) {
        sxb[i] = (float*)(dynsm + i*SXB);
        sbb[i] = (float*)(dynsm + NBUF*SXB + i*SBB);
    }

    const int tid = threadIdx.x;
    const int w = tid >> 5, lane = tid & 31;
    const int tig = lane & 3, grp = lane >> 2;
    const int b  = blockIdx.z;
    const int y0 = blockIdx.y * 4;
    const int x0 = blockIdx.x * 64;
    const int wrow = w >> 1;
    const int wx = (w & 1) * 32;

    float acc[2][8][4];
    #pragma unroll
    for (int mt = 0; mt < 2; mt++)
        #pragma unroll
        for (int nt = 0; nt < 8; nt++)
            #pragma unroll
            for (int r = 0; r < 4; r++) acc[mt][nt][r] = 0.f;

    const float* xb = x + (size_t)b*CI*PLANE;
    const float* fbase = g_filters + (size_t)b*NCH*9*CCH*CO;

    auto stage = [&](int cc, int buf) {
        float* sx = sxb[buf];
        for (int i = tid; i < CCH*6*18; i += 256) {
            int ci  = i / 108;
            int r2  = i - ci*108;
            int row = r2 / 18;
            int c16 = r2 - row*18;
            int gy  = y0 - 1 + row;
            int gxs = x0 - 4 + c16*4;
            int ok  = ((unsigned)gy < (unsigned)HH) &
                      ((unsigned)gxs <= (unsigned)(WW-4));
            const float* src = ok ? (xb + (size_t)(cc*CCH+ci)*PLANE + gy*WW + gxs)
                                  : xb;
            cpa16(sx + ci*SXPS + row*SBROW + c16*4, src, ok ? 16 : 0);
        }
        float* sb = sbb[buf];
        const float* fsrc = fbase + (size_t)cc*9*CCH*CO;
        for (int j = tid; j < 72*16; j += 256) {
            int row = j >> 4, c = j & 15;
            cpa16(sb + row*SBROW + c*4, fsrc + row*CO + c*4, 16);
        }
    };

    auto compute = [&](int buf) {
        const uint32_t* ax = (const uint32_t*)(sxb[buf]) +
                             tig*SXPS + wrow*SBROW + (wx + grp + 3);
        const uint32_t* bb = (const uint32_t*)(sbb[buf]) + tig*SBROW + grp;
        #pragma unroll
        for (int tap = 0; tap < 9; tap++) {
            const int tg = tap / 3, tloc = tap - tg*3;
            const uint32_t* ap = ax + tg*SBROW + tloc;
            const uint32_t* bp = bb + tap*(CCH*SBROW);
            uint32_t a[2][4];
            #pragma unroll
            for (int mt = 0; mt < 2; mt++) {
                a[mt][0] = ap[mt*16];
                a[mt][1] = ap[mt*16 + 8];
                a[mt][2] = ap[mt*16 + 4*SXPS];
                a[mt][3] = ap[mt*16 + 4*SXPS + 8];
            }
            uint32_t bf[8][2];
            #pragma unroll
            for (int nt = 0; nt < 8; nt++) {
                bf[nt][0] = bp[nt*8];
                bf[nt][1] = bp[nt*8 + 4*SBROW];
            }
            #pragma unroll
            for (int mt = 0; mt < 2; mt++)
                #pragma unroll
                for (int nt = 0; nt < 8; nt++)
                    mma8(acc[mt][nt], a[mt], bf[nt]);
        }
    };

    // ---- pipeline: stage(ch+1) ahead, ONE barrier per chunk ----
    // Buffer-reuse safety (NBUF=3): stage(ch+1) writes buf (ch+1)%3,
    // last read by compute(ch-2); all warps passed iter ch-1's barrier,
    // which is after their compute(ch-2). cp.async visibility: stage(ch)
    // completed by wait_group 1 at iter ch, published by the barrier.
    stage(0, 0);
    cpa_commit();
    int buf = 0;
    for (int ch = 0; ch < NCH; ch++) {
        if (ch + 1 < NCH) {
            int nb = buf + 1 == NBUF ? 0 : buf + 1;
            stage(ch + 1, nb);
        }
        cpa_commit();
        cpa_wait1();
        __syncthreads();
        compute(buf);
        buf = buf + 1 == NBUF ? 0 : buf + 1;
    }

    // ---- epilogue: store raw conv + fused GroupNorm partials ----
    const int gy = y0 + wrow;
    float s[8], q[8];
    #pragma unroll
    for (int g = 0; g < 8; g++) { s[g] = 0.f; q[g] = 0.f; }

    float* ob = out + (size_t)b*CO*PLANE + gy*WW;
    #pragma unroll
    for (int mt = 0; mt < 2; mt++) {
        #pragma unroll
        for (int nt = 0; nt < 8; nt++) {
            #pragma unroll
            for (int r = 0; r < 4; r++) {
                float v = acc[mt][nt][r];
                int gx = x0 + wx + mt*16 + grp + ((r >> 1) << 3);
                int co = nt*8 + tig*2 + (r & 1);
                ob[co*PLANE + gx] = v;
                s[nt] += v;
                q[nt] += v*v;
            }
        }
    }
    #pragma unroll
    for (int o = 16; o > 0; o >>= 1) {
        #pragma unroll
        for (int g = 0; g < 8; g++) {
            s[g] += __shfl_down_sync(~0u, s[g], o);
            q[g] += __shfl_down_sync(~0u, q[g], o);
        }
    }
    if (lane == 0) {
        #pragma unroll
        for (int g = 0; g < 8; g++) {
            atomicAdd(&g_stats[b][g][0], s[g]);
            atomicAdd(&g_stats[b][g][1], q[g]);
        }
    }
}

// ============================================================
// K4: in-place GroupNorm + affine + LeakyReLU
// ============================================================
__global__ void norm_kernel(float* __restrict__ out,
                            const float* __restrict__ gamma,
                            const float* __restrict__ beta) {
    int idx = blockIdx.x * 256 + threadIdx.x;
    const int PL4 = PLANE / 4;
    int clin = idx / PL4;
    int co = clin % CO;
    int b  = clin / CO;
    int g  = co >> 3;
    float s = g_stats[b][g][0], q = g_stats[b][g][1];
    const float invN = 1.f / (float)(CPG * PLANE);
    float mean = s * invN;
    float var  = q * invN - mean*mean;
    float rstd = rsqrtf(var + EPS);
    float ga = gamma[co], be = beta[co];
    float4 v = ((float4*)out)[idx];
    float* pv = (float*)&v;
    #pragma unroll
    for (int i = 0; i < 4; i++) {
        float yn = (pv[i] - mean) * rstd * ga + be;
        pv[i] = yn >= 0.f ? yn : SLOPE * yn;
    }
    ((float4*)out)[idx] = v;
}

// ============================================================
extern "C" void kernel_launch(void* const* d_in, const int* in_sizes, int n_in,
                              void* d_out, int out_size) {
    const float* x  = (const float*)d_in[0];
    const float* w1 = (const float*)d_in[1];
    const float* w2 = (const float*)d_in[2];
    const float* b2 = (const float*)d_in[3];
    const float* W  = (const float*)d_in[4];
    const float* ga = (const float*)d_in[5];
    const float* be = (const float*)d_in[6];
    float* out = (float*)d_out;

    cudaFuncSetAttribute(conv_kernel,
                         cudaFuncAttributeMaxDynamicSharedMemorySize, SMEM_DYN);

    pool_kernel<<<B*CI, 256>>>(x);
    attn_kernel<<<1, 256>>>(w1, w2, b2);
    filt_kernel<<<(B*NCH*9*CCH*CO)/256, 256>>>(W);
    conv_kernel<<<dim3(3, 48, B), 256, SMEM_DYN>>>(x, out);
    norm_kernel<<<(B*CO*PLANE/4)/256, 256>>>(out, ga, be);
}

// round 7
// speedup vs baseline: 1.0991x; 1.0991x over previous
#include <cuda_runtime.h>
#include <cstdint>

#define B 16
#define CI 64
#define CO 64
#define HH 192
#define WW 192
#define KDY 4
#define HID 17
#define GROUPS 8
#define CPG 8
#define PLANE (HH*WW)
#define TEMPERATURE 30.0f
#define EPS 1e-5f
#define SLOPE 0.01f

// conv tiling
#define CCH 8                      // ci per chunk
#define NCH 8                      // chunks
#define SXPS 296                   // sx stride per ci (floats): 4 rows * 72 + 8 pad
#define SXB (CCH*SXPS*4)           // 9472 B per x buffer
#define SBB (9*CCH*CO*4)           // 18432 B per filter buffer (swizzled, no pad)
#define SBUF (SXB+SBB)             // 27904
#define SMEM_DYN (2*SBUF)          // 55808 B

// ---- device scratch ----
__device__ float g_pooled[B][CI];
__device__ float g_attn[B][KDY];
__device__ __align__(16) float g_filters[B*NCH*9*CCH*CO];  // [b][cc][tap][ci8][co]
__device__ float g_stats[B][GROUPS][2];

__device__ __forceinline__ uint32_t f2tf32(float v) {
    uint32_t u;
    asm("cvt.rna.tf32.f32 %0, %1;" : "=r"(u) : "f"(v));
    return u;
}
__device__ __forceinline__ void mma8(float* c, const uint32_t* a, const uint32_t* b) {
    asm volatile(
        "mma.sync.aligned.m16n8k8.row.col.f32.tf32.tf32.f32 "
        "{%0,%1,%2,%3}, {%4,%5,%6,%7}, {%8,%9}, {%0,%1,%2,%3};"
        : "+f"(c[0]), "+f"(c[1]), "+f"(c[2]), "+f"(c[3])
        : "r"(a[0]), "r"(a[1]), "r"(a[2]), "r"(a[3]), "r"(b[0]), "r"(b[1]));
}
__device__ __forceinline__ void cpa16(void* dst, const void* src, int sz) {
    uint32_t d = (uint32_t)__cvta_generic_to_shared(dst);
    asm volatile("cp.async.cg.shared.global [%0], [%1], 16, %2;"
                 :: "r"(d), "l"(src), "r"(sz) : "memory");
}
__device__ __forceinline__ void cpa_commit() {
    asm volatile("cp.async.commit_group;" ::: "memory");
}
__device__ __forceinline__ void cpa_wait1() {
    asm volatile("cp.async.wait_group 1;" ::: "memory");
}

// ============================================================
// K1: global average pool
// ============================================================
__global__ void pool_kernel(const float* __restrict__ x) {
    int bc = blockIdx.x;
    const float4* p = (const float4*)(x + (size_t)bc * PLANE);
    float s = 0.f;
    for (int i = threadIdx.x; i < PLANE/4; i += 256) {
        float4 v = p[i];
        s += v.x + v.y + v.z + v.w;
    }
    __shared__ float sm[8];
    #pragma unroll
    for (int o = 16; o > 0; o >>= 1) s += __shfl_down_sync(~0u, s, o);
    if ((threadIdx.x & 31) == 0) sm[threadIdx.x >> 5] = s;
    __syncthreads();
    if (threadIdx.x == 0) {
        float t = 0.f;
        #pragma unroll
        for (int w = 0; w < 8; w++) t += sm[w];
        g_pooled[bc / CI][bc % CI] = t / (float)PLANE;
    }
}

// ============================================================
// K2a: attention MLP + softmax; zero group stats
// ============================================================
__global__ void attn_kernel(const float* __restrict__ w1,
                            const float* __restrict__ w2,
                            const float* __restrict__ b2) {
    int t = threadIdx.x;
    if (t < B * GROUPS * 2) ((float*)g_stats)[t] = 0.f;
    if (t < B) {
        float h[HID];
        #pragma unroll
        for (int j = 0; j < HID; j++) {
            float a = 0.f;
            #pragma unroll 8
            for (int c = 0; c < CI; c++) a += g_pooled[t][c] * w1[j*CI + c];
            h[j] = a > 0.f ? a : 0.f;
        }
        float sc[KDY];
        float m = -1e30f;
        #pragma unroll
        for (int k = 0; k < KDY; k++) {
            float a = b2[k];
            #pragma unroll
            for (int j = 0; j < HID; j++) a += h[j] * w2[k*HID + j];
            sc[k] = a / TEMPERATURE;
            m = fmaxf(m, sc[k]);
        }
        float se = 0.f;
        #pragma unroll
        for (int k = 0; k < KDY; k++) { sc[k] = expf(sc[k] - m); se += sc[k]; }
        #pragma unroll
        for (int k = 0; k < KDY; k++) g_attn[t][k] = sc[k] / se;
    }
}

// ============================================================
// K2b: filter synthesis -> staging layout [b][cc][tap][ci8][co]
// ============================================================
__global__ void filt_kernel(const float* __restrict__ W) {
    int idx = blockIdx.x * 256 + threadIdx.x;
    int co  = idx & 63;
    int ci8 = (idx >> 6) & 7;
    int t3  = idx >> 9;
    int tap = t3 % 9;
    int t4  = t3 / 9;
    int cc  = t4 & 7;
    int b   = t4 >> 3;
    int ci  = cc*CCH + ci8;
    const int ks = CO*CI*9;
    float a0 = g_attn[b][0], a1 = g_attn[b][1], a2 = g_attn[b][2], a3 = g_attn[b][3];
    int wb = (co*CI + ci)*9 + tap;                // W[k][co][ci][tap]
    float f = a0*W[wb] + a1*W[wb+ks] + a2*W[wb+2*ks] + a3*W[wb+3*ks];
    g_filters[idx] = __uint_as_float(f2tf32(f));
}

// ============================================================
// K3: implicit-GEMM tf32 conv. m32n32 warp tiles, 32 warps/SM.
// CTA: sample b, M=128 px (2 rows x 64 cols), N=64 co, 8 warps:
//   warp w: nw=w>>2 (co half), mw=w&3 -> row=mw&1, col32=(mw>>1)*32.
// cp.async double-buffered, 2 syncs/chunk. B tile XOR-swizzled.
// ============================================================
__global__ void __launch_bounds__(256, 4)
conv_kernel(const float* __restrict__ x, float* __restrict__ out) {
    extern __shared__ __align__(16) unsigned char dynsm[];

    const int tid = threadIdx.x;
    const int w = tid >> 5, lane = tid & 31;
    const int tig = lane & 3, grp = lane >> 2;
    const int nw = w >> 2, mw = w & 3;
    const int row_w = mw & 1, col32 = (mw >> 1) * 32;
    const int b  = blockIdx.z;
    const int y0 = blockIdx.y * 2;
    const int x0 = blockIdx.x * 64;

    float acc[2][4][4];
    #pragma unroll
    for (int mt = 0; mt < 2; mt++)
        #pragma unroll
        for (int nt = 0; nt < 4; nt++)
            #pragma unroll
            for (int r = 0; r < 4; r++) acc[mt][nt][r] = 0.f;

    const float* xb = x + (size_t)b*CI*PLANE;
    const float* fbase = g_filters + (size_t)b*NCH*9*CCH*CO;

    auto stage = [&](int cc, int buf) {
        float* sx = (float*)(dynsm + buf*SBUF);
        // x tile: 8ci x 4rows x 18 16B-chunks (cols x0-4 .. x0+67)
        for (int i = tid; i < CCH*4*18; i += 256) {
            int ci  = i / 72;
            int r2  = i - ci*72;
            int row = r2 / 18;
            int c16 = r2 - row*18;
            int gy  = y0 - 1 + row;
            int gxs = x0 - 4 + c16*4;
            int ok  = ((unsigned)gy < (unsigned)HH) &
                      ((unsigned)gxs <= (unsigned)(WW-4));
            const float* src = ok ? (xb + (size_t)(cc*CCH+ci)*PLANE + gy*WW + gxs)
                                  : xb;
            cpa16(sx + ci*SXPS + row*72 + c16*4, src, ok ? 16 : 0);
        }
        // filters: 72 rows x 64 co, XOR-swizzled col = co ^ ((row&3)<<3)
        float* sb = (float*)(dynsm + buf*SBUF + SXB);
        const float* fsrc = fbase + (size_t)cc*9*CCH*CO;
        for (int j = tid; j < 72*16; j += 256) {
            int row = j >> 4, co4 = (j & 15) * 4;
            cpa16(sb + row*64 + (co4 ^ ((row & 3) << 3)),
                  fsrc + row*CO + co4, 16);
        }
    };

    auto compute = [&](int buf) {
        const uint32_t* ax = (const uint32_t*)(dynsm + buf*SBUF) +
                             tig*SXPS + row_w*72 + (col32 + grp + 3);
        // b-frag col with swizzle folded in: nw*32 + ((nt^tig)<<3) + grp
        const uint32_t* bb = (const uint32_t*)(dynsm + buf*SBUF + SXB) +
                             tig*64 + nw*32 + grp;
        #pragma unroll
        for (int tap = 0; tap < 9; tap++) {
            const int tg = tap / 3, tloc = tap - tg*3;
            const uint32_t* ap = ax + tg*72 + tloc;
            const uint32_t* bp = bb + tap*(8*64);
            uint32_t a[2][4];
            #pragma unroll
            for (int mt = 0; mt < 2; mt++) {
                // PTX m16n8k8 A order: a0=(r,k) a1=(r+8,k) a2=(r,k+4) a3=(r+8,k+4)
                a[mt][0] = ap[mt*16];
                a[mt][1] = ap[mt*16 + 8];
                a[mt][2] = ap[mt*16 + 4*SXPS];
                a[mt][3] = ap[mt*16 + 4*SXPS + 8];
            }
            uint32_t bf[4][2];
            #pragma unroll
            for (int nt = 0; nt < 4; nt++) {
                int csw = ((nt ^ tig) << 3);
                bf[nt][0] = bp[csw];
                bf[nt][1] = bp[csw + 4*64];
            }
            #pragma unroll
            for (int mt = 0; mt < 2; mt++)
                #pragma unroll
                for (int nt = 0; nt < 4; nt++)
                    mma8(acc[mt][nt], a[mt], bf[nt]);
        }
    };

    // ---- pipeline: double buffer, stage(ch+1) overlaps compute(ch) ----
    stage(0, 0);
    cpa_commit();
    for (int ch = 0; ch < NCH; ch++) {
        if (ch + 1 < NCH) stage(ch + 1, (ch + 1) & 1);
        cpa_commit();
        cpa_wait1();
        __syncthreads();
        compute(ch & 1);
        __syncthreads();
    }

    // ---- epilogue: store raw conv + fused GroupNorm partials ----
    float s[4], q[4];
    #pragma unroll
    for (int g = 0; g < 4; g++) { s[g] = 0.f; q[g] = 0.f; }

    float* ob = out + (size_t)b*CO*PLANE + (y0 + row_w)*WW;
    #pragma unroll
    for (int mt = 0; mt < 2; mt++) {
        #pragma unroll
        for (int nt = 0; nt < 4; nt++) {
            #pragma unroll
            for (int r = 0; r < 4; r++) {
                float v = acc[mt][nt][r];
                int gx = x0 + col32 + mt*16 + grp + ((r >> 1) << 3);
                int co = nw*32 + nt*8 + tig*2 + (r & 1);
                ob[co*PLANE + gx] = v;
                s[nt] += v;
                q[nt] += v*v;
            }
        }
    }
    #pragma unroll
    for (int o = 16; o > 0; o >>= 1) {
        #pragma unroll
        for (int g = 0; g < 4; g++) {
            s[g] += __shfl_down_sync(~0u, s[g], o);
            q[g] += __shfl_down_sync(~0u, q[g], o);
        }
    }
    if (lane == 0) {
        #pragma unroll
        for (int g = 0; g < 4; g++) {
            atomicAdd(&g_stats[b][nw*4 + g][0], s[g]);
            atomicAdd(&g_stats[b][nw*4 + g][1], q[g]);
        }
    }
}

// ============================================================
// K4: in-place GroupNorm + affine + LeakyReLU
// ============================================================
__global__ void norm_kernel(float* __restrict__ out,
                            const float* __restrict__ gamma,
                            const float* __restrict__ beta) {
    int idx = blockIdx.x * 256 + threadIdx.x;
    const int PL4 = PLANE / 4;
    int clin = idx / PL4;
    int co = clin % CO;
    int b  = clin / CO;
    int g  = co >> 3;
    float s = g_stats[b][g][0], q = g_stats[b][g][1];
    const float invN = 1.f / (float)(CPG * PLANE);
    float mean = s * invN;
    float var  = q * invN - mean*mean;
    float rstd = rsqrtf(var + EPS);
    float ga = gamma[co], be = beta[co];
    float4 v = ((float4*)out)[idx];
    float* pv = (float*)&v;
    #pragma unroll
    for (int i = 0; i < 4; i++) {
        float yn = (pv[i] - mean) * rstd * ga + be;
        pv[i] = yn >= 0.f ? yn : SLOPE * yn;
    }
    ((float4*)out)[idx] = v;
}

// ============================================================
extern "C" void kernel_launch(void* const* d_in, const int* in_sizes, int n_in,
                              void* d_out, int out_size) {
    const float* x  = (const float*)d_in[0];
    const float* w1 = (const float*)d_in[1];
    const float* w2 = (const float*)d_in[2];
    const float* b2 = (const float*)d_in[3];
    const float* W  = (const float*)d_in[4];
    const float* ga = (const float*)d_in[5];
    const float* be = (const float*)d_in[6];
    float* out = (float*)d_out;

    cudaFuncSetAttribute(conv_kernel,
                         cudaFuncAttributeMaxDynamicSharedMemorySize, SMEM_DYN);

    pool_kernel<<<B*CI, 256>>>(x);
    attn_kernel<<<1, 256>>>(w1, w2, b2);
    filt_kernel<<<(B*NCH*9*CCH*CO)/256, 256>>>(W);
    conv_kernel<<<dim3(3, 96, B), 256, SMEM_DYN>>>(x, out);
    norm_kernel<<<(B*CO*PLANE/4)/256, 256>>>(out, ga, be);
}

// round 8
// speedup vs baseline: 1.1721x; 1.0665x over previous
#include <cuda_runtime.h>
#include <cuda_fp16.h>
#include <cstdint>

#define B 16
#define CI 64
#define CO 64
#define HH 192
#define WW 192
#define KDY 4
#define HID 17
#define GROUPS 8
#define CPG 8
#define PLANE (HH*WW)
#define TEMPERATURE 30.0f
#define EPS 1e-5f
#define SLOPE 0.01f

// conv tiling: 4 chunks of 16 ci, fp16 operands
#define NCH 4
#define SXHB 9216                   // x tile: 288 px * 32B
#define SBHB 18432                  // filters: 72 rows * 64 half2
#define SBUF (SXHB+SBHB)            // 27648
#define SMEM_DYN (2*SBUF)           // 55296 -> 4 CTAs/SM

// ---- device scratch ----
__device__ float   g_ppart[B*4*36*16];                 // pool partials [b][cc][pblk][ci16]
__device__ float   g_pooled[B][CI];
__device__ float   g_attn[B][KDY];
__device__ __align__(16) __half g_xh[(size_t)B*4*PLANE*16];   // [b][cc][pix][ci16]
__device__ __align__(16) uint32_t g_fh[B*4*9*8*64];    // [b][cc][tap][kp][co'] half2, swizzled
__device__ float   g_stats[B][GROUPS][2];

__device__ __forceinline__ void mma16(float* c, const uint32_t* a, const uint32_t* b) {
    asm volatile(
        "mma.sync.aligned.m16n8k16.row.col.f32.f16.f16.f32 "
        "{%0,%1,%2,%3}, {%4,%5,%6,%7}, {%8,%9}, {%0,%1,%2,%3};"
        : "+f"(c[0]), "+f"(c[1]), "+f"(c[2]), "+f"(c[3])
        : "r"(a[0]), "r"(a[1]), "r"(a[2]), "r"(a[3]), "r"(b[0]), "r"(b[1]));
}
__device__ __forceinline__ void cpa16(void* dst, const void* src, int sz) {
    uint32_t d = (uint32_t)__cvta_generic_to_shared(dst);
    asm volatile("cp.async.cg.shared.global [%0], [%1], 16, %2;"
                 :: "r"(d), "l"(src), "r"(sz) : "memory");
}
__device__ __forceinline__ void cpa_commit() {
    asm volatile("cp.async.commit_group;" ::: "memory");
}
__device__ __forceinline__ void cpa_wait1() {
    asm volatile("cp.async.wait_group 1;" ::: "memory");
}

// ============================================================
// K1: convert x -> fp16 [b][cc][pix][ci16]  + pool partials
// grid (36, 4, B), block 256; each block: 1024 pixels of (b,cc)
// ============================================================
__global__ void __launch_bounds__(256)
convert_pool_kernel(const float* __restrict__ x) {
    int b = blockIdx.z, cc = blockIdx.y, pb = blockIdx.x;
    int t = threadIdx.x;
    const float* xp = x + ((size_t)b*CI + cc*16)*PLANE + pb*1024;
    __half* outp = g_xh + (((size_t)(b*4+cc))*PLANE + pb*1024)*16;

    float s[16];
    #pragma unroll
    for (int i = 0; i < 16; i++) s[i] = 0.f;

    #pragma unroll
    for (int it = 0; it < 4; it++) {
        int p = it*256 + t;
        uint32_t h2[8];
        #pragma unroll
        for (int ci = 0; ci < 16; ci += 2) {
            float v0 = xp[(size_t)ci*PLANE + p];
            float v1 = xp[(size_t)(ci+1)*PLANE + p];
            s[ci] += v0; s[ci+1] += v1;
            __half2 h = __floats2half2_rn(v0, v1);
            h2[ci>>1] = *(uint32_t*)&h;
        }
        uint4* o = (uint4*)(outp + (size_t)p*16);
        o[0] = make_uint4(h2[0], h2[1], h2[2], h2[3]);
        o[1] = make_uint4(h2[4], h2[5], h2[6], h2[7]);
    }
    // reduce 16 sums across block
    __shared__ float red[8][16];
    #pragma unroll
    for (int o = 16; o > 0; o >>= 1)
        #pragma unroll
        for (int i = 0; i < 16; i++) s[i] += __shfl_down_sync(~0u, s[i], o);
    if ((t & 31) == 0)
        #pragma unroll
        for (int i = 0; i < 16; i++) red[t>>5][i] = s[i];
    __syncthreads();
    if (t < 16) {
        float tot = 0.f;
        #pragma unroll
        for (int w = 0; w < 8; w++) tot += red[w][t];
        g_ppart[(((b*4+cc)*36) + pb)*16 + t] = tot;
    }
}

// ============================================================
// K2a: finish pool + attention MLP + softmax; zero group stats
// ============================================================
__global__ void attn_kernel(const float* __restrict__ w1,
                            const float* __restrict__ w2,
                            const float* __restrict__ b2) {
    int t = threadIdx.x;
    if (t < B * GROUPS * 2) ((float*)g_stats)[t] = 0.f;
    // reduce partials: 1024 (b,ci) pairs, 4 per thread
    #pragma unroll
    for (int j = 0; j < 4; j++) {
        int idx = t*4 + j;
        int b = idx >> 6, ci = idx & 63;
        int cc = ci >> 4, i = ci & 15;
        float a = 0.f;
        const float* pp = g_ppart + ((b*4+cc)*36)*16 + i;
        #pragma unroll 4
        for (int p = 0; p < 36; p++) a += pp[p*16];
        g_pooled[b][ci] = a / (float)PLANE;
    }
    __syncthreads();
    if (t < B) {
        float h[HID];
        #pragma unroll
        for (int j = 0; j < HID; j++) {
            float a = 0.f;
            #pragma unroll 8
            for (int c = 0; c < CI; c++) a += g_pooled[t][c] * w1[j*CI + c];
            h[j] = a > 0.f ? a : 0.f;
        }
        float sc[KDY];
        float m = -1e30f;
        #pragma unroll
        for (int k = 0; k < KDY; k++) {
            float a = b2[k];
            #pragma unroll
            for (int j = 0; j < HID; j++) a += h[j] * w2[k*HID + j];
            sc[k] = a / TEMPERATURE;
            m = fmaxf(m, sc[k]);
        }
        float se = 0.f;
        #pragma unroll
        for (int k = 0; k < KDY; k++) { sc[k] = expf(sc[k] - m); se += sc[k]; }
        #pragma unroll
        for (int k = 0; k < KDY; k++) g_attn[t][k] = sc[k] / se;
    }
}

// ============================================================
// K2b: filter synthesis -> fp16 half2, pre-swizzled:
// g_fh[b][cc][tap][kp][co'] where co' = co ^ ((kp&3)<<3),
// half2 = (F[ci=cc*16+2kp], F[ci=+1]) for output co.
// ============================================================
__global__ void filt_kernel(const float* __restrict__ W) {
    int idx = blockIdx.x * 256 + threadIdx.x;
    int cos  = idx & 63;
    int kp   = (idx >> 6) & 7;
    int tap  = (idx >> 9) % 9;
    int rest = idx / (64*8*9);
    int cc = rest & 3, b = rest >> 2;
    int co  = cos ^ ((kp & 3) << 3);
    int ci0 = cc*16 + 2*kp;
    const int ks = CO*CI*9;
    float a0 = g_attn[b][0], a1 = g_attn[b][1], a2 = g_attn[b][2], a3 = g_attn[b][3];
    int w0 = (co*CI + ci0)*9 + tap;
    int w1 = w0 + 9;                                  // ci0+1
    float f0 = a0*W[w0] + a1*W[w0+ks] + a2*W[w0+2*ks] + a3*W[w0+3*ks];
    float f1 = a0*W[w1] + a1*W[w1+ks] + a2*W[w1+2*ks] + a3*W[w1+3*ks];
    __half2 h = __floats2half2_rn(f0, f1);
    g_fh[idx] = *(uint32_t*)&h;
}

// ============================================================
// K3: implicit-GEMM fp16 conv (mma.m16n8k16), m32n32 warp tiles,
// 4 CTAs/SM. 4 chunks of 16 ci, 9 taps each. cp.async 2-buffer.
// A smem: [pix(4x72)][ci16] half, 16B-half XOR swizzle on bit2(pix).
// B smem: [tap][kp][co'] half2, swizzle pre-applied in gmem.
// ============================================================
__global__ void __launch_bounds__(256, 4)
conv_kernel(float* __restrict__ out) {
    extern __shared__ __align__(128) unsigned char dynsm[];

    const int tid = threadIdx.x;
    const int w = tid >> 5, lane = tid & 31;
    const int tig = lane & 3, grp = lane >> 2;
    const int nw = w >> 2, mw = w & 3;
    const int row_w = mw & 1, col32 = (mw >> 1) * 32;
    const int b  = blockIdx.z;
    const int y0 = blockIdx.y * 2;
    const int x0 = blockIdx.x * 64;

    float acc[2][4][4];
    #pragma unroll
    for (int mt = 0; mt < 2; mt++)
        #pragma unroll
        for (int nt = 0; nt < 4; nt++)
            #pragma unroll
            for (int r = 0; r < 4; r++) acc[mt][nt][r] = 0.f;

    auto stage = [&](int cc, int buf) {
        unsigned char* sx = dynsm + buf*SBUF;
        const __half* xh = g_xh + (size_t)(b*4+cc)*PLANE*16;
        // x tile: 4 rows x 72 cols, 2 x 16B per pixel
        for (int i = tid; i < 576; i += 256) {
            int half = i & 1;
            int col  = (i >> 1) % 72;
            int row  = (i >> 1) / 72;
            int gy = y0 - 1 + row;
            int gx = x0 - 4 + col;
            int pix = row*72 + col;
            int ok = ((unsigned)gy < (unsigned)HH) & ((unsigned)gx < (unsigned)WW);
            const __half* src = ok ? (xh + ((size_t)(gy*WW+gx))*16 + half*8) : xh;
            int dh = half ^ ((pix >> 2) & 1);
            cpa16(sx + pix*32 + dh*16, src, ok ? 16 : 0);
        }
        // filters: linear 18432B copy
        unsigned char* sb = dynsm + buf*SBUF + SXHB;
        const unsigned char* fsrc =
            (const unsigned char*)(g_fh + (size_t)(b*4+cc)*72*64);
        for (int i = tid; i < 1152; i += 256)
            cpa16(sb + i*16, fsrc + i*16, 16);
    };

    auto compute = [&](int buf) {
        const unsigned char* sx = dynsm + buf*SBUF;
        const uint32_t* sb = (const uint32_t*)(dynsm + buf*SBUF + SXHB);
        #pragma unroll
        for (int tap = 0; tap < 9; tap++) {
            const int tg = tap / 3, tloc = tap - tg*3;
            int pixb = (row_w + tg)*72 + col32 + grp + 3 + tloc;
            uint32_t sw = ((pixb >> 2) & 1) << 2;
            const uint32_t* a0p =
                (const uint32_t*)(sx + pixb*32 + ((tig ^ sw) << 2));
            const uint32_t* a1p =
                (const uint32_t*)((uintptr_t)a0p ^ 16u);
            uint32_t a[2][4];
            #pragma unroll
            for (int mt = 0; mt < 2; mt++) {
                a[mt][0] = a0p[mt*128];         // (row grp,   k 0-7)
                a[mt][1] = a0p[mt*128 + 64];    // (row grp+8, k 0-7)
                a[mt][2] = a1p[mt*128];         // (row grp,   k 8-15)
                a[mt][3] = a1p[mt*128 + 64];    // (row grp+8, k 8-15)
            }
            int boff = (tap*8 + tig)*64 + nw*32 + grp;
            uint32_t bf[4][2];
            #pragma unroll
            for (int nt = 0; nt < 4; nt++) {
                int csw = (nt ^ tig) << 3;
                bf[nt][0] = sb[boff + csw];
                bf[nt][1] = sb[boff + 256 + csw];
            }
            #pragma unroll
            for (int mt = 0; mt < 2; mt++)
                #pragma unroll
                for (int nt = 0; nt < 4; nt++)
                    mma16(acc[mt][nt], a[mt], bf[nt]);
        }
    };

    stage(0, 0);
    cpa_commit();
    for (int ch = 0; ch < NCH; ch++) {
        if (ch + 1 < NCH) stage(ch + 1, (ch + 1) & 1);
        cpa_commit();
        cpa_wait1();
        __syncthreads();
        compute(ch & 1);
        __syncthreads();
    }

    // ---- epilogue: store raw conv + fused GroupNorm partials ----
    float s[4], q[4];
    #pragma unroll
    for (int g = 0; g < 4; g++) { s[g] = 0.f; q[g] = 0.f; }

    float* ob = out + (size_t)b*CO*PLANE + (y0 + row_w)*WW;
    #pragma unroll
    for (int mt = 0; mt < 2; mt++) {
        #pragma unroll
        for (int nt = 0; nt < 4; nt++) {
            #pragma unroll
            for (int r = 0; r < 4; r++) {
                float v = acc[mt][nt][r];
                int gx = x0 + col32 + mt*16 + grp + ((r >> 1) << 3);
                int co = nw*32 + nt*8 + tig*2 + (r & 1);
                ob[co*PLANE + gx] = v;
                s[nt] += v;
                q[nt] += v*v;
            }
        }
    }
    #pragma unroll
    for (int o = 16; o > 0; o >>= 1) {
        #pragma unroll
        for (int g = 0; g < 4; g++) {
            s[g] += __shfl_down_sync(~0u, s[g], o);
            q[g] += __shfl_down_sync(~0u, q[g], o);
        }
    }
    if (lane == 0) {
        #pragma unroll
        for (int g = 0; g < 4; g++) {
            atomicAdd(&g_stats[b][nw*4 + g][0], s[g]);
            atomicAdd(&g_stats[b][nw*4 + g][1], q[g]);
        }
    }
}

// ============================================================
// K4: in-place GroupNorm + affine + LeakyReLU
// ============================================================
__global__ void norm_kernel(float* __restrict__ out,
                            const float* __restrict__ gamma,
                            const float* __restrict__ beta) {
    int idx = blockIdx.x * 256 + threadIdx.x;
    const int PL4 = PLANE / 4;
    int clin = idx / PL4;
    int co = clin % CO;
    int b  = clin / CO;
    int g  = co >> 3;
    float s = g_stats[b][g][0], q = g_stats[b][g][1];
    const float invN = 1.f / (float)(CPG * PLANE);
    float mean = s * invN;
    float var  = q * invN - mean*mean;
    float rstd = rsqrtf(var + EPS);
    float ga = gamma[co], be = beta[co];
    float4 v = ((float4*)out)[idx];
    float* pv = (float*)&v;
    #pragma unroll
    for (int i = 0; i < 4; i++) {
        float yn = (pv[i] - mean) * rstd * ga + be;
        pv[i] = yn >= 0.f ? yn : SLOPE * yn;
    }
    ((float4*)out)[idx] = v;
}

// ============================================================
extern "C" void kernel_launch(void* const* d_in, const int* in_sizes, int n_in,
                              void* d_out, int out_size) {
    const float* x  = (const float*)d_in[0];
    const float* w1 = (const float*)d_in[1];
    const float* w2 = (const float*)d_in[2];
    const float* b2 = (const float*)d_in[3];
    const float* W  = (const float*)d_in[4];
    const float* ga = (const float*)d_in[5];
    const float* be = (const float*)d_in[6];
    float* out = (float*)d_out;

    cudaFuncSetAttribute(conv_kernel,
                         cudaFuncAttributeMaxDynamicSharedMemorySize, SMEM_DYN);

    convert_pool_kernel<<<dim3(36, 4, B), 256>>>(x);
    attn_kernel<<<1, 256>>>(w1, w2, b2);
    filt_kernel<<<(B*4*9*8*64)/256, 256>>>(W);
    conv_kernel<<<dim3(3, 96, B), 256, SMEM_DYN>>>(out);
    norm_kernel<<<(B*CO*PLANE/4)/256, 256>>>(out, ga, be);
}

// round 9
// speedup vs baseline: 1.1917x; 1.0167x over previous
#include <cuda_runtime.h>
#include <cuda_fp16.h>
#include <cstdint>

#define B 16
#define CI 64
#define CO 64
#define HH 192
#define WW 192
#define KDY 4
#define HID 17
#define GROUPS 8
#define CPG 8
#define PLANE (HH*WW)
#define TEMPERATURE 30.0f
#define EPS 1e-5f
#define SLOPE 0.01f

// conv tiling: 4 chunks of 16 ci, fp16 operands
#define NCH 4
#define SXHB 9216                   // x tile: 288 px * 32B
#define SBHB 18432                  // filters: 9 taps * 2 khalf * 64 n * 16B
#define SBUF (SXHB+SBHB)            // 27648
#define SMEM_DYN (2*SBUF)           // 55296 -> 4 CTAs/SM

// ---- device scratch ----
__device__ float   g_ppart[B*4*36*16];                 // pool partials [b][cc][pblk][ci16]
__device__ float   g_pooled[B][CI];
__device__ float   g_attn[B][KDY];
__device__ __align__(16) __half g_xh[(size_t)B*4*PLANE*16];   // [b][cc][pix][ci16]
__device__ __align__(16) uint32_t g_fh[B*4*9*2*64*4];  // [b][cc][tap][khalf][n][k8] (u32=half2)
__device__ float   g_stats[B][GROUPS][2];

__device__ __forceinline__ void mma16(float* c, const uint32_t* a, const uint32_t* b) {
    asm volatile(
        "mma.sync.aligned.m16n8k16.row.col.f32.f16.f16.f32 "
        "{%0,%1,%2,%3}, {%4,%5,%6,%7}, {%8,%9}, {%0,%1,%2,%3};"
        : "+f"(c[0]), "+f"(c[1]), "+f"(c[2]), "+f"(c[3])
        : "r"(a[0]), "r"(a[1]), "r"(a[2]), "r"(a[3]), "r"(b[0]), "r"(b[1]));
}
__device__ __forceinline__ void ldsm4(uint32_t* r, uint32_t addr) {
    asm volatile("ldmatrix.sync.aligned.m8n8.x4.shared.b16 {%0,%1,%2,%3}, [%4];"
                 : "=r"(r[0]), "=r"(r[1]), "=r"(r[2]), "=r"(r[3]) : "r"(addr));
}
__device__ __forceinline__ void cpa16(void* dst, const void* src, int sz) {
    uint32_t d = (uint32_t)__cvta_generic_to_shared(dst);
    asm volatile("cp.async.cg.shared.global [%0], [%1], 16, %2;"
                 :: "r"(d), "l"(src), "r"(sz) : "memory");
}
__device__ __forceinline__ void cpa_commit() {
    asm volatile("cp.async.commit_group;" ::: "memory");
}
__device__ __forceinline__ void cpa_wait1() {
    asm volatile("cp.async.wait_group 1;" ::: "memory");
}

// ============================================================
// K1: convert x -> fp16 [b][cc][pix][ci16]  + pool partials
// ============================================================
__global__ void __launch_bounds__(256)
convert_pool_kernel(const float* __restrict__ x) {
    int b = blockIdx.z, cc = blockIdx.y, pb = blockIdx.x;
    int t = threadIdx.x;
    const float* xp = x + ((size_t)b*CI + cc*16)*PLANE + pb*1024;
    __half* outp = g_xh + (((size_t)(b*4+cc))*PLANE + pb*1024)*16;

    float s[16];
    #pragma unroll
    for (int i = 0; i < 16; i++) s[i] = 0.f;

    #pragma unroll
    for (int it = 0; it < 4; it++) {
        int p = it*256 + t;
        uint32_t h2[8];
        #pragma unroll
        for (int ci = 0; ci < 16; ci += 2) {
            float v0 = xp[(size_t)ci*PLANE + p];
            float v1 = xp[(size_t)(ci+1)*PLANE + p];
            s[ci] += v0; s[ci+1] += v1;
            __half2 h = __floats2half2_rn(v0, v1);
            h2[ci>>1] = *(uint32_t*)&h;
        }
        uint4* o = (uint4*)(outp + (size_t)p*16);
        o[0] = make_uint4(h2[0], h2[1], h2[2], h2[3]);
        o[1] = make_uint4(h2[4], h2[5], h2[6], h2[7]);
    }
    __shared__ float red[8][16];
    #pragma unroll
    for (int o = 16; o > 0; o >>= 1)
        #pragma unroll
        for (int i = 0; i < 16; i++) s[i] += __shfl_down_sync(~0u, s[i], o);
    if ((t & 31) == 0)
        #pragma unroll
        for (int i = 0; i < 16; i++) red[t>>5][i] = s[i];
    __syncthreads();
    if (t < 16) {
        float tot = 0.f;
        #pragma unroll
        for (int w = 0; w < 8; w++) tot += red[w][t];
        g_ppart[(((b*4+cc)*36) + pb)*16 + t] = tot;
    }
}

// ============================================================
// K2a: finish pool + attention MLP + softmax; zero group stats
// ============================================================
__global__ void attn_kernel(const float* __restrict__ w1,
                            const float* __restrict__ w2,
                            const float* __restrict__ b2) {
    int t = threadIdx.x;
    if (t < B * GROUPS * 2) ((float*)g_stats)[t] = 0.f;
    #pragma unroll
    for (int j = 0; j < 4; j++) {
        int idx = t*4 + j;
        int b = idx >> 6, ci = idx & 63;
        int cc = ci >> 4, i = ci & 15;
        float a = 0.f;
        const float* pp = g_ppart + ((b*4+cc)*36)*16 + i;
        #pragma unroll 4
        for (int p = 0; p < 36; p++) a += pp[p*16];
        g_pooled[b][ci] = a / (float)PLANE;
    }
    __syncthreads();
    if (t < B) {
        float h[HID];
        #pragma unroll
        for (int j = 0; j < HID; j++) {
            float a = 0.f;
            #pragma unroll 8
            for (int c = 0; c < CI; c++) a += g_pooled[t][c] * w1[j*CI + c];
            h[j] = a > 0.f ? a : 0.f;
        }
        float sc[KDY];
        float m = -1e30f;
        #pragma unroll
        for (int k = 0; k < KDY; k++) {
            float a = b2[k];
            #pragma unroll
            for (int j = 0; j < HID; j++) a += h[j] * w2[k*HID + j];
            sc[k] = a / TEMPERATURE;
            m = fmaxf(m, sc[k]);
        }
        float se = 0.f;
        #pragma unroll
        for (int k = 0; k < KDY; k++) { sc[k] = expf(sc[k] - m); se += sc[k]; }
        #pragma unroll
        for (int k = 0; k < KDY; k++) g_attn[t][k] = sc[k] / se;
    }
}

// ============================================================
// K2b: filter synthesis -> n-major 16B rows for ldmatrix:
// g_fh[b][cc][tap][khalf][n][k2] : half2(F[ci0], F[ci0+1]),
// ci0 = cc*16 + khalf*8 + 2*k2, n = c_out.
// ============================================================
__global__ void filt_kernel(const float* __restrict__ W) {
    int idx = blockIdx.x * 256 + threadIdx.x;
    int k2    = idx & 3;
    int n     = (idx >> 2) & 63;
    int khalf = (idx >> 8) & 1;
    int tap   = (idx >> 9) % 9;
    int rest  = idx / 4608;
    int cc = rest & 3, b = rest >> 2;
    int ci0 = cc*16 + khalf*8 + 2*k2;
    const int ks = CO*CI*9;
    float a0 = g_attn[b][0], a1 = g_attn[b][1], a2 = g_attn[b][2], a3 = g_attn[b][3];
    int w0 = (n*CI + ci0)*9 + tap;
    int w1 = w0 + 9;                                  // ci0+1
    float f0 = a0*W[w0] + a1*W[w0+ks] + a2*W[w0+2*ks] + a3*W[w0+3*ks];
    float f1 = a0*W[w1] + a1*W[w1+ks] + a2*W[w1+2*ks] + a3*W[w1+3*ks];
    __half2 h = __floats2half2_rn(f0, f1);
    g_fh[idx] = *(uint32_t*)&h;
}

// ============================================================
// K3: implicit-GEMM fp16 conv, ldmatrix + mma.m16n8k16.
// m32n32 warp tiles, 4 CTAs/SM, 4 chunks of 16 ci.
// A smem: [pix][ci16], 16B halves XOR-swizzled on bit2(pix).
// B smem: [tap][khalf][n][k8] 16B rows (conflict-free, no swizzle).
// ============================================================
__global__ void __launch_bounds__(256, 4)
conv_kernel(float* __restrict__ out) {
    extern __shared__ __align__(128) unsigned char dynsm[];
    const uint32_t smb = (uint32_t)__cvta_generic_to_shared(dynsm);

    const int tid = threadIdx.x;
    const int w = tid >> 5, lane = tid & 31;
    const int tig = lane & 3, grp = lane >> 2;
    const int nw = w >> 2, mw = w & 3;
    const int row_w = mw & 1, col32 = (mw >> 1) * 32;
    const int b  = blockIdx.z;
    const int y0 = blockIdx.y * 2;
    const int x0 = blockIdx.x * 64;

    // ldmatrix lane constants (A): matrix m = lane>>3
    const int pixoff  = ((lane >> 3) & 1) * 8 + (lane & 7);
    const int halfbit = (lane >> 4) & 1;
    // B lane address: n = nw*32 + ((lane>>4)&1)*8 + (lane&7), khalf=(lane>>3)&1
    const uint32_t blane = (((lane >> 3) & 1) << 10) +
                           (nw*32 + ((lane >> 4) & 1)*8 + (lane & 7)) * 16;

    float acc[2][4][4];
    #pragma unroll
    for (int mt = 0; mt < 2; mt++)
        #pragma unroll
        for (int nt = 0; nt < 4; nt++)
            #pragma unroll
            for (int r = 0; r < 4; r++) acc[mt][nt][r] = 0.f;

    auto stage = [&](int cc, int buf) {
        unsigned char* sx = dynsm + buf*SBUF;
        const __half* xh = g_xh + (size_t)(b*4+cc)*PLANE*16;
        for (int i = tid; i < 576; i += 256) {
            int half = i & 1;
            int col  = (i >> 1) % 72;
            int row  = (i >> 1) / 72;
            int gy = y0 - 1 + row;
            int gx = x0 - 4 + col;
            int pix = row*72 + col;
            int ok = ((unsigned)gy < (unsigned)HH) & ((unsigned)gx < (unsigned)WW);
            const __half* src = ok ? (xh + ((size_t)(gy*WW+gx))*16 + half*8) : xh;
            int dh = half ^ ((pix >> 2) & 1);
            cpa16(sx + pix*32 + dh*16, src, ok ? 16 : 0);
        }
        unsigned char* sb = dynsm + buf*SBUF + SXHB;
        const unsigned char* fsrc =
            (const unsigned char*)(g_fh + (size_t)(b*4+cc)*4608);
        for (int i = tid; i < 1152; i += 256)
            cpa16(sb + i*16, fsrc + i*16, 16);
    };

    auto compute = [&](int buf) {
        const uint32_t sxa = smb + buf*SBUF;
        const uint32_t sba = smb + buf*SBUF + SXHB + blane;
        #pragma unroll
        for (int tap = 0; tap < 9; tap++) {
            const int tg = tap / 3, tloc = tap - tg*3;
            const int P = (row_w + tg)*72 + col32 + 3 + tloc + pixoff;
            uint32_t a[2][4];
            #pragma unroll
            for (int mt = 0; mt < 2; mt++) {
                int pix = P + mt*16;
                ldsm4(a[mt], sxa + pix*32 + (((halfbit ^ (pix >> 2)) & 1) << 4));
            }
            uint32_t bfr[8];
            ldsm4(bfr,     sba + tap*2048);
            ldsm4(bfr + 4, sba + tap*2048 + 256);
            #pragma unroll
            for (int mt = 0; mt < 2; mt++)
                #pragma unroll
                for (int nt = 0; nt < 4; nt++)
                    mma16(acc[mt][nt], a[mt], &bfr[nt*2]);
        }
    };

    stage(0, 0);
    cpa_commit();
    for (int ch = 0; ch < NCH; ch++) {
        if (ch + 1 < NCH) stage(ch + 1, (ch + 1) & 1);
        cpa_commit();
        cpa_wait1();
        __syncthreads();
        compute(ch & 1);
        __syncthreads();
    }

    // ---- epilogue: store raw conv + fused GroupNorm partials ----
    float s[4], q[4];
    #pragma unroll
    for (int g = 0; g < 4; g++) { s[g] = 0.f; q[g] = 0.f; }

    float* ob = out + (size_t)b*CO*PLANE + (y0 + row_w)*WW;
    #pragma unroll
    for (int mt = 0; mt < 2; mt++) {
        #pragma unroll
        for (int nt = 0; nt < 4; nt++) {
            #pragma unroll
            for (int r = 0; r < 4; r++) {
                float v = acc[mt][nt][r];
                int gx = x0 + col32 + mt*16 + grp + ((r >> 1) << 3);
                int co = nw*32 + nt*8 + tig*2 + (r & 1);
                ob[co*PLANE + gx] = v;
                s[nt] += v;
                q[nt] += v*v;
            }
        }
    }
    #pragma unroll
    for (int o = 16; o > 0; o >>= 1) {
        #pragma unroll
        for (int g = 0; g < 4; g++) {
            s[g] += __shfl_down_sync(~0u, s[g], o);
            q[g] += __shfl_down_sync(~0u, q[g], o);
        }
    }
    if (lane == 0) {
        #pragma unroll
        for (int g = 0; g < 4; g++) {
            atomicAdd(&g_stats[b][nw*4 + g][0], s[g]);
            atomicAdd(&g_stats[b][nw*4 + g][1], q[g]);
        }
    }
}

// ============================================================
// K4: in-place GroupNorm + affine + LeakyReLU
// ============================================================
__global__ void norm_kernel(float* __restrict__ out,
                            const float* __restrict__ gamma,
                            const float* __restrict__ beta) {
    int idx = blockIdx.x * 256 + threadIdx.x;
    const int PL4 = PLANE / 4;
    int clin = idx / PL4;
    int co = clin % CO;
    int b  = clin / CO;
    int g  = co >> 3;
    float s = g_stats[b][g][0], q = g_stats[b][g][1];
    const float invN = 1.f / (float)(CPG * PLANE);
    float mean = s * invN;
    float var  = q * invN - mean*mean;
    float rstd = rsqrtf(var + EPS);
    float ga = gamma[co], be = beta[co];
    float4 v = ((float4*)out)[idx];
    float* pv = (float*)&v;
    #pragma unroll
    for (int i = 0; i < 4; i++) {
        float yn = (pv[i] - mean) * rstd * ga + be;
        pv[i] = yn >= 0.f ? yn : SLOPE * yn;
    }
    ((float4*)out)[idx] = v;
}

// ============================================================
extern "C" void kernel_launch(void* const* d_in, const int* in_sizes, int n_in,
                              void* d_out, int out_size) {
    const float* x  = (const float*)d_in[0];
    const float* w1 = (const float*)d_in[1];
    const float* w2 = (const float*)d_in[2];
    const float* b2 = (const float*)d_in[3];
    const float* W  = (const float*)d_in[4];
    const float* ga = (const float*)d_in[5];
    const float* be = (const float*)d_in[6];
    float* out = (float*)d_out;

    cudaFuncSetAttribute(conv_kernel,
                         cudaFuncAttributeMaxDynamicSharedMemorySize, SMEM_DYN);

    convert_pool_kernel<<<dim3(36, 4, B), 256>>>(x);
    attn_kernel<<<1, 256>>>(w1, w2, b2);
    filt_kernel<<<(B*4*9*2*64*4)/256, 256>>>(W);
    conv_kernel<<<dim3(3, 96, B), 256, SMEM_DYN>>>(out);
    norm_kernel<<<(B*CO*PLANE/4)/256, 256>>>(out, ga, be);
}

// round 10
// speedup vs baseline: 1.2375x; 1.0384x over previous
#include <cuda_runtime.h>
#include <cuda_fp16.h>
#include <cstdint>

#define B 16
#define CI 64
#define CO 64
#define HH 192
#define WW 192
#define KDY 4
#define HID 17
#define GROUPS 8
#define CPG 8
#define PLANE (HH*WW)
#define TEMPERATURE 30.0f
#define EPS 1e-5f
#define SLOPE 0.01f

// padded fp16 x: rows 0..193 (=gy+1), cols 0..199 (=gx+4), halo zero
#define WP 200
#define HP 194
#define PPLANE (HP*WP)

// conv tiling: 4 chunks of 16 ci
#define NCH 4
#define SXHB 9216                   // x tile: 288 px * 32B
#define SBHB 18432                  // filters: 9*2*64*16B
#define SBUF (SXHB+SBHB)            // 27648
#define SMEM_DYN (2*SBUF + 32)      // + 2 mbarriers

// ---- device scratch ----
__device__ float   g_ppart[B*4*36*16];
__device__ float   g_pooled[B][CI];
__device__ float   g_attn[B][KDY];
__device__ __align__(16) __half g_xh[(size_t)B*4*PPLANE*16];  // [b][cc][pgpix][ci16] swizzled
__device__ __align__(16) uint32_t g_fh[B*4*9*2*64*4];  // [b][cc][tap][khalf][n][k8]
__device__ float   g_stats[B][GROUPS][2];

__device__ __forceinline__ void mma16(float* c, const uint32_t* a, const uint32_t* b) {
    asm volatile(
        "mma.sync.aligned.m16n8k16.row.col.f32.f16.f16.f32 "
        "{%0,%1,%2,%3}, {%4,%5,%6,%7}, {%8,%9}, {%0,%1,%2,%3};"
        : "+f"(c[0]), "+f"(c[1]), "+f"(c[2]), "+f"(c[3])
        : "r"(a[0]), "r"(a[1]), "r"(a[2]), "r"(a[3]), "r"(b[0]), "r"(b[1]));
}
__device__ __forceinline__ void ldsm4(uint32_t* r, uint32_t addr) {
    asm volatile("ldmatrix.sync.aligned.m8n8.x4.shared.b16 {%0,%1,%2,%3}, [%4];"
                 : "=r"(r[0]), "=r"(r[1]), "=r"(r[2]), "=r"(r[3]) : "r"(addr));
}
__device__ __forceinline__ void bulk_cp(uint32_t dst, const void* src,
                                        uint32_t bytes, uint32_t mbar) {
    asm volatile(
        "cp.async.bulk.shared::cluster.global.mbarrier::complete_tx::bytes "
        "[%0], [%1], %2, [%3];"
        :: "r"(dst), "l"(src), "r"(bytes), "r"(mbar) : "memory");
}
__device__ __forceinline__ void mbar_init(uint32_t a, uint32_t c) {
    asm volatile("mbarrier.init.shared.b64 [%0], %1;" :: "r"(a), "r"(c) : "memory");
}
__device__ __forceinline__ void mbar_expect(uint32_t a, uint32_t bytes) {
    asm volatile("mbarrier.arrive.expect_tx.shared.b64 _, [%0], %1;"
                 :: "r"(a), "r"(bytes) : "memory");
}
__device__ __forceinline__ void mbar_wait(uint32_t a, uint32_t par) {
    asm volatile("{\n\t.reg .pred P;\n"
                 "WAIT_%=:\n\t"
                 "mbarrier.try_wait.parity.acquire.cta.shared::cta.b64 P, [%0], %1;\n\t"
                 "@!P bra WAIT_%=;\n\t}" :: "r"(a), "r"(par) : "memory");
}

// ============================================================
// K1: convert x -> padded swizzled fp16 [b][cc][pg][ci16] + pool partials
// ============================================================
__global__ void __launch_bounds__(256)
convert_pool_kernel(const float* __restrict__ x) {
    int b = blockIdx.z, cc = blockIdx.y, pb = blockIdx.x;
    int t = threadIdx.x;
    const float* xp = x + ((size_t)b*CI + cc*16)*PLANE + pb*1024;
    __half* outbase = g_xh + (size_t)(b*4+cc)*PPLANE*16;

    float s[16];
    #pragma unroll
    for (int i = 0; i < 16; i++) s[i] = 0.f;

    #pragma unroll
    for (int it = 0; it < 4; it++) {
        int p = it*256 + t;
        int pp = pb*1024 + p;
        int gy = pp / WW, gx = pp - gy*WW;
        int pg = (gy+1)*WP + gx + 4;
        uint32_t h2[8];
        #pragma unroll
        for (int ci = 0; ci < 16; ci += 2) {
            float v0 = xp[(size_t)ci*PLANE + p];
            float v1 = xp[(size_t)(ci+1)*PLANE + p];
            s[ci] += v0; s[ci+1] += v1;
            __half2 h = __floats2half2_rn(v0, v1);
            h2[ci>>1] = *(uint32_t*)&h;
        }
        int sw = (pg >> 2) & 1;
        uint4* o = (uint4*)(outbase + (size_t)pg*16);
        o[0 ^ sw] = make_uint4(h2[0], h2[1], h2[2], h2[3]);
        o[1 ^ sw] = make_uint4(h2[4], h2[5], h2[6], h2[7]);
    }
    __shared__ float red[8][16];
    #pragma unroll
    for (int o = 16; o > 0; o >>= 1)
        #pragma unroll
        for (int i = 0; i < 16; i++) s[i] += __shfl_down_sync(~0u, s[i], o);
    if ((t & 31) == 0)
        #pragma unroll
        for (int i = 0; i < 16; i++) red[t>>5][i] = s[i];
    __syncthreads();
    if (t < 16) {
        float tot = 0.f;
        #pragma unroll
        for (int w = 0; w < 8; w++) tot += red[w][t];
        g_ppart[(((b*4+cc)*36) + pb)*16 + t] = tot;
    }
}

// ============================================================
// K2a: finish pool + attention MLP + softmax; zero group stats
// ============================================================
__global__ void attn_kernel(const float* __restrict__ w1,
                            const float* __restrict__ w2,
                            const float* __restrict__ b2) {
    int t = threadIdx.x;
    if (t < B * GROUPS * 2) ((float*)g_stats)[t] = 0.f;
    #pragma unroll
    for (int j = 0; j < 4; j++) {
        int idx = t*4 + j;
        int b = idx >> 6, ci = idx & 63;
        int cc = ci >> 4, i = ci & 15;
        float a = 0.f;
        const float* pp = g_ppart + ((b*4+cc)*36)*16 + i;
        #pragma unroll 4
        for (int p = 0; p < 36; p++) a += pp[p*16];
        g_pooled[b][ci] = a / (float)PLANE;
    }
    __syncthreads();
    if (t < B) {
        float h[HID];
        #pragma unroll
        for (int j = 0; j < HID; j++) {
            float a = 0.f;
            #pragma unroll 8
            for (int c = 0; c < CI; c++) a += g_pooled[t][c] * w1[j*CI + c];
            h[j] = a > 0.f ? a : 0.f;
        }
        float sc[KDY];
        float m = -1e30f;
        #pragma unroll
        for (int k = 0; k < KDY; k++) {
            float a = b2[k];
            #pragma unroll
            for (int j = 0; j < HID; j++) a += h[j] * w2[k*HID + j];
            sc[k] = a / TEMPERATURE;
            m = fmaxf(m, sc[k]);
        }
        float se = 0.f;
        #pragma unroll
        for (int k = 0; k < KDY; k++) { sc[k] = expf(sc[k] - m); se += sc[k]; }
        #pragma unroll
        for (int k = 0; k < KDY; k++) g_attn[t][k] = sc[k] / se;
    }
}

// ============================================================
// K2b: filter synthesis -> n-major 16B rows for ldmatrix
// ============================================================
__global__ void filt_kernel(const float* __restrict__ W) {
    int idx = blockIdx.x * 256 + threadIdx.x;
    int k2    = idx & 3;
    int n     = (idx >> 2) & 63;
    int khalf = (idx >> 8) & 1;
    int tap   = (idx >> 9) % 9;
    int rest  = idx / 4608;
    int cc = rest & 3, b = rest >> 2;
    int ci0 = cc*16 + khalf*8 + 2*k2;
    const int ks = CO*CI*9;
    float a0 = g_attn[b][0], a1 = g_attn[b][1], a2 = g_attn[b][2], a3 = g_attn[b][3];
    int w0 = (n*CI + ci0)*9 + tap;
    int w1 = w0 + 9;
    float f0 = a0*W[w0] + a1*W[w0+ks] + a2*W[w0+2*ks] + a3*W[w0+3*ks];
    float f1 = a0*W[w1] + a1*W[w1+ks] + a2*W[w1+2*ks] + a3*W[w1+3*ks];
    __half2 h = __floats2half2_rn(f0, f1);
    g_fh[idx] = *(uint32_t*)&h;
}

// ============================================================
// K3: implicit-GEMM fp16 conv; staging via cp.async.bulk (5 copies
// per chunk from one thread) + mbarrier complete_tx. ldmatrix+mma.
// ============================================================
__global__ void __launch_bounds__(256, 4)
conv_kernel(float* __restrict__ out) {
    extern __shared__ __align__(128) unsigned char dynsm[];
    const uint32_t smb = (uint32_t)__cvta_generic_to_shared(dynsm);
    const uint32_t mb0 = smb + 2*SBUF;

    const int tid = threadIdx.x;
    const int w = tid >> 5, lane = tid & 31;
    const int tig = lane & 3, grp = lane >> 2;
    const int nw = w >> 2, mw = w & 3;
    const int row_w = mw & 1, col32 = (mw >> 1) * 32;
    const int b  = blockIdx.z;
    const int y0 = blockIdx.y * 2;
    const int x0 = blockIdx.x * 64;

    const int pixoff  = ((lane >> 3) & 1) * 8 + (lane & 7);
    const int halfbit = (lane >> 4) & 1;
    const uint32_t blane = (((lane >> 3) & 1) << 10) +
                           (nw*32 + ((lane >> 4) & 1)*8 + (lane & 7)) * 16;

    float acc[2][4][4];
    #pragma unroll
    for (int mt = 0; mt < 2; mt++)
        #pragma unroll
        for (int nt = 0; nt < 4; nt++)
            #pragma unroll
            for (int r = 0; r < 4; r++) acc[mt][nt][r] = 0.f;

    if (tid == 0) { mbar_init(mb0, 1); mbar_init(mb0 + 8, 1); }
    __syncthreads();

    auto stage = [&](int cc, int buf) {   // single-thread
        uint32_t bar = mb0 + buf*8;
        mbar_expect(bar, SBUF);
        bulk_cp(smb + buf*SBUF + SXHB,
                g_fh + (size_t)(b*4+cc)*4608, SBHB, bar);
        const __half* xs = g_xh +
            ((size_t)(b*4+cc)*PPLANE + (size_t)y0*WP + x0)*16;
        #pragma unroll
        for (int r = 0; r < 4; r++)
            bulk_cp(smb + buf*SBUF + r*2304, xs + (size_t)r*WP*16, 2304, bar);
    };

    auto compute = [&](int buf) {
        const uint32_t sxa = smb + buf*SBUF;
        const uint32_t sba = smb + buf*SBUF + SXHB + blane;
        #pragma unroll
        for (int tap = 0; tap < 9; tap++) {
            const int tg = tap / 3, tloc = tap - tg*3;
            const int P = (row_w + tg)*72 + col32 + 3 + tloc + pixoff;
            uint32_t a[2][4];
            #pragma unroll
            for (int mt = 0; mt < 2; mt++) {
                int pix = P + mt*16;
                ldsm4(a[mt], sxa + pix*32 + (((halfbit ^ (pix >> 2)) & 1) << 4));
            }
            uint32_t bfr[8];
            ldsm4(bfr,     sba + tap*2048);
            ldsm4(bfr + 4, sba + tap*2048 + 256);
            #pragma unroll
            for (int mt = 0; mt < 2; mt++)
                #pragma unroll
                for (int nt = 0; nt < 4; nt++)
                    mma16(acc[mt][nt], a[mt], &bfr[nt*2]);
        }
    };

    if (tid == 0) stage(0, 0);
    for (int ch = 0; ch < NCH; ch++) {
        if (tid == 0 && ch + 1 < NCH) stage(ch + 1, (ch + 1) & 1);
        mbar_wait(mb0 + (ch & 1)*8, (ch >> 1) & 1);
        compute(ch & 1);
        __syncthreads();   // buffer + mbarrier recycle safety
    }

    // ---- epilogue: store raw conv + fused GroupNorm partials ----
    float s[4], q[4];
    #pragma unroll
    for (int g = 0; g < 4; g++) { s[g] = 0.f; q[g] = 0.f; }

    float* ob = out + (size_t)b*CO*PLANE + (y0 + row_w)*WW;
    #pragma unroll
    for (int mt = 0; mt < 2; mt++) {
        #pragma unroll
        for (int nt = 0; nt < 4; nt++) {
            #pragma unroll
            for (int r = 0; r < 4; r++) {
                float v = acc[mt][nt][r];
                int gx = x0 + col32 + mt*16 + grp + ((r >> 1) << 3);
                int co = nw*32 + nt*8 + tig*2 + (r & 1);
                ob[co*PLANE + gx] = v;
                s[nt] += v;
                q[nt] += v*v;
            }
        }
    }
    #pragma unroll
    for (int o = 16; o > 0; o >>= 1) {
        #pragma unroll
        for (int g = 0; g < 4; g++) {
            s[g] += __shfl_down_sync(~0u, s[g], o);
            q[g] += __shfl_down_sync(~0u, q[g], o);
        }
    }
    if (lane == 0) {
        #pragma unroll
        for (int g = 0; g < 4; g++) {
            atomicAdd(&g_stats[b][nw*4 + g][0], s[g]);
            atomicAdd(&g_stats[b][nw*4 + g][1], q[g]);
        }
    }
}

// ============================================================
// K4: in-place GroupNorm + affine + LeakyReLU
// ============================================================
__global__ void norm_kernel(float* __restrict__ out,
                            const float* __restrict__ gamma,
                            const float* __restrict__ beta) {
    int idx = blockIdx.x * 256 + threadIdx.x;
    const int PL4 = PLANE / 4;
    int clin = idx / PL4;
    int co = clin % CO;
    int b  = clin / CO;
    int g  = co >> 3;
    float s = g_stats[b][g][0], q = g_stats[b][g][1];
    const float invN = 1.f / (float)(CPG * PLANE);
    float mean = s * invN;
    float var  = q * invN - mean*mean;
    float rstd = rsqrtf(var + EPS);
    float ga = gamma[co], be = beta[co];
    float4 v = ((float4*)out)[idx];
    float* pv = (float*)&v;
    #pragma unroll
    for (int i = 0; i < 4; i++) {
        float yn = (pv[i] - mean) * rstd * ga + be;
        pv[i] = yn >= 0.f ? yn : SLOPE * yn;
    }
    ((float4*)out)[idx] = v;
}

// ============================================================
extern "C" void kernel_launch(void* const* d_in, const int* in_sizes, int n_in,
                              void* d_out, int out_size) {
    const float* x  = (const float*)d_in[0];
    const float* w1 = (const float*)d_in[1];
    const float* w2 = (const float*)d_in[2];
    const float* b2 = (const float*)d_in[3];
    const float* W  = (const float*)d_in[4];
    const float* ga = (const float*)d_in[5];
    const float* be = (const float*)d_in[6];
    float* out = (float*)d_out;

    cudaFuncSetAttribute(conv_kernel,
                         cudaFuncAttributeMaxDynamicSharedMemorySize, SMEM_DYN);

    convert_pool_kernel<<<dim3(36, 4, B), 256>>>(x);
    attn_kernel<<<1, 256>>>(w1, w2, b2);
    filt_kernel<<<(B*4*9*2*64*4)/256, 256>>>(W);
    conv_kernel<<<dim3(3, 96, B), 256, SMEM_DYN>>>(out);
    norm_kernel<<<(B*CO*PLANE/4)/256, 256>>>(out, ga, be);
}